// round 12
// baseline (speedup 1.0000x reference)
#include <cuda_runtime.h>
#include <math.h>

// Problem constants: x[8, 256, 128, 128] fp32
#define NPLANES 2048
#define HW      16384
#define FULL    0xffffffffu

// Scratch (no allocations allowed)
__device__ float g_p[NPLANES];   // per-plane mean of x
__device__ float g_a[NPLANES];   // sigmoid attention scales

__device__ __forceinline__ float4 zero4() { return make_float4(0.f, 0.f, 0.f, 0.f); }

__device__ __forceinline__ float halo_l(float4 v, int lane) {
    float l = __shfl_up_sync(FULL, v.w, 1);
    return (lane == 0) ? 0.f : l;
}
__device__ __forceinline__ float halo_r(float4 v, int lane) {
    float r = __shfl_down_sync(FULL, v.x, 1);
    return (lane == 31) ? 0.f : r;
}

// 3x3 conv producing 4 outputs from float4 rows + halo scalars.
__device__ __forceinline__ float4 conv_row(float4 t, float tl, float tr,
                                            float4 m, float ml, float mr,
                                            float4 b, float bl, float br,
                                            const float* w, float init) {
    float4 o;
    o.x = init; o.y = init; o.z = init; o.w = init;
    o.x = fmaf(tl,  w[0], o.x); o.x = fmaf(t.x, w[1], o.x); o.x = fmaf(t.y, w[2], o.x);
    o.y = fmaf(t.x, w[0], o.y); o.y = fmaf(t.y, w[1], o.y); o.y = fmaf(t.z, w[2], o.y);
    o.z = fmaf(t.y, w[0], o.z); o.z = fmaf(t.z, w[1], o.z); o.z = fmaf(t.w, w[2], o.z);
    o.w = fmaf(t.z, w[0], o.w); o.w = fmaf(t.w, w[1], o.w); o.w = fmaf(tr,  w[2], o.w);
    o.x = fmaf(ml,  w[3], o.x); o.x = fmaf(m.x, w[4], o.x); o.x = fmaf(m.y, w[5], o.x);
    o.y = fmaf(m.x, w[3], o.y); o.y = fmaf(m.y, w[4], o.y); o.y = fmaf(m.z, w[5], o.y);
    o.z = fmaf(m.y, w[3], o.z); o.z = fmaf(m.z, w[4], o.z); o.z = fmaf(m.w, w[5], o.z);
    o.w = fmaf(m.z, w[3], o.w); o.w = fmaf(m.w, w[4], o.w); o.w = fmaf(mr,  w[5], o.w);
    o.x = fmaf(bl,  w[6], o.x); o.x = fmaf(b.x, w[7], o.x); o.x = fmaf(b.y, w[8], o.x);
    o.y = fmaf(b.x, w[6], o.y); o.y = fmaf(b.y, w[7], o.y); o.y = fmaf(b.z, w[8], o.y);
    o.z = fmaf(b.y, w[6], o.z); o.z = fmaf(b.z, w[7], o.z); o.z = fmaf(b.w, w[8], o.z);
    o.w = fmaf(b.z, w[6], o.w); o.w = fmaf(b.w, w[7], o.w); o.w = fmaf(br,  w[8], o.w);
    return o;
}

// ---------------------------------------------------------------------------
// K1: per-plane mean (proven 23.4us @ 75% DRAM). 2048 blocks x 256 threads.
// ---------------------------------------------------------------------------
__global__ void __launch_bounds__(256) mean_kernel(const float* __restrict__ x) {
    int plane = blockIdx.x;
    const float4* xp = (const float4*)(x + (size_t)plane * HW);
    int tid = threadIdx.x;
    float s = 0.f;
#pragma unroll
    for (int k = 0; k < 16; k++) {
        float4 v = xp[tid + k * 256];
        s += (v.x + v.y) + (v.z + v.w);
    }
#pragma unroll
    for (int o = 16; o; o >>= 1) s += __shfl_xor_sync(FULL, s, o);
    __shared__ float red[8];
    if ((tid & 31) == 0) red[tid >> 5] = s;
    __syncthreads();
    if (tid == 0) {
        float t = 0.f;
#pragma unroll
        for (int i = 0; i < 8; i++) t += red[i];
        g_p[plane] = t * (1.0f / 16384.0f);
    }
}

// ---------------------------------------------------------------------------
// K2 (fused SE attention): h = leaky(p @ w1^T); a = sigmoid(h @ w2^T).
// ---------------------------------------------------------------------------
__global__ void __launch_bounds__(256) attn_kernel(const float* __restrict__ w1,
                                                    const float* __restrict__ w2) {
    int b = blockIdx.x;
    __shared__ float ps[256];
    __shared__ float hs[64];
    int tid = threadIdx.x;
    ps[tid] = g_p[b * 256 + tid];
    __syncthreads();
    {
        int j = tid >> 2, part = tid & 3;
        const float* wr = w1 + j * 256 + part * 64;
        const float* pr = ps + part * 64;
        float s = 0.f;
#pragma unroll
        for (int cc = 0; cc < 64; cc++) s = fmaf(pr[cc], wr[cc], s);
        s += __shfl_xor_sync(FULL, s, 1);
        s += __shfl_xor_sync(FULL, s, 2);
        if (part == 0) hs[j] = (s > 0.f) ? s : 0.01f * s;
    }
    __syncthreads();
    {
        const float* wr = w2 + tid * 64;
        float s = 0.f;
#pragma unroll
        for (int j = 0; j < 64; j++) s = fmaf(hs[j], wr[j], s);
        g_a[b * 256 + tid] = 1.0f / (1.0f + expf(-s));
    }
}

// ---------------------------------------------------------------------------
// K3 supermain: ONE block per plane (reverse order, riding mean's L2 tail).
// The conv is computed exactly ONCE: conv(a*x)+bias with a-folded weights,
// outputs staged in a 64KB dynamic-smem plane buffer, sum/sumsq accumulated
// in registers, ONE barrier pair for the InstanceNorm reduction, then each
// thread reads back its own staged values, normalizes + leaky, stores.
// Warp j owns rows [16j, 16j+16), processed as two batched 8-row segments
// (10-row front-batched loads each, MLP=10).
// ---------------------------------------------------------------------------
__global__ void __launch_bounds__(256) supermain_kernel(const float* __restrict__ x,
                                                         const float* __restrict__ rw,
                                                         const float* __restrict__ rb,
                                                         float* __restrict__ out) {
    extern __shared__ float so[];              // 16384 floats = full plane of conv outputs
    float4* sov = (float4*)so;
    int plane = (NPLANES - 1) - blockIdx.x;
    int c = plane & 255;
    int tid = threadIdx.x, lane = tid & 31, wj = tid >> 5;
    int R0 = wj * 16;
    const float4* xp = (const float4*)(x + (size_t)plane * HW);
    float4* op = (float4*)(out + (size_t)plane * HW);

    float a = g_a[plane];
    float bias = rb[c];
    float w[9];
#pragma unroll
    for (int i = 0; i < 9; i++) w[i] = a * rw[c * 9 + i];

    float ssum = 0.f, ssq = 0.f;

    // Two 8-row segments, each with front-batched 10-row strip loads.
#pragma unroll
    for (int seg = 0; seg < 2; seg++) {
        int S0 = R0 + seg * 8;
        float4 v[10];
        v[0] = (S0 == 0) ? zero4() : xp[(S0 - 1) * 32 + lane];
#pragma unroll
        for (int i = 1; i < 9; i++) v[i] = xp[(S0 - 1 + i) * 32 + lane];
        v[9] = (S0 + 8 > 127) ? zero4() : xp[(S0 + 8) * 32 + lane];

        float l[3], r[3];
        l[0] = halo_l(v[0], lane); r[0] = halo_r(v[0], lane);
        l[1] = halo_l(v[1], lane); r[1] = halo_r(v[1], lane);

#pragma unroll
        for (int i = 0; i < 8; i++) {
            l[(i + 2) % 3] = halo_l(v[i + 2], lane);
            r[(i + 2) % 3] = halo_r(v[i + 2], lane);
            float4 o = conv_row(v[i],     l[i % 3],       r[i % 3],
                                v[i + 1], l[(i + 1) % 3], r[(i + 1) % 3],
                                v[i + 2], l[(i + 2) % 3], r[(i + 2) % 3],
                                w, bias);
            ssum += ((o.x + o.y) + (o.z + o.w));
            ssq = fmaf(o.x, o.x, ssq); ssq = fmaf(o.y, o.y, ssq);
            ssq = fmaf(o.z, o.z, ssq); ssq = fmaf(o.w, o.w, ssq);
            sov[(S0 + i) * 32 + lane] = o;     // stage raw conv output
        }
    }

    // InstanceNorm reduction (single barrier pair — never inside hot loops)
#pragma unroll
    for (int o = 16; o; o >>= 1) {
        ssum += __shfl_xor_sync(FULL, ssum, o);
        ssq  += __shfl_xor_sync(FULL, ssq,  o);
    }
    __shared__ float r1[8], r2[8];
    __shared__ float s_mu, s_rs;
    if (lane == 0) { r1[wj] = ssum; r2[wj] = ssq; }
    __syncthreads();
    if (tid == 0) {
        float t1 = 0.f, t2 = 0.f;
#pragma unroll
        for (int i = 0; i < 8; i++) { t1 += r1[i]; t2 += r2[i]; }
        float mu = t1 * (1.0f / 16384.0f);
        float var = t2 * (1.0f / 16384.0f) - mu * mu;
        s_mu = mu;
        s_rs = rsqrtf(var + 1e-5f);
    }
    __syncthreads();
    float mu = s_mu, rstd = s_rs;

    // Read back own staged rows, normalize + leaky, coalesced streaming stores
#pragma unroll
    for (int i = 0; i < 16; i++) {
        float4 v = sov[(R0 + i) * 32 + lane];
        float4 o;
        o.x = (v.x - mu) * rstd; o.x = fmaxf(o.x, 0.01f * o.x);
        o.y = (v.y - mu) * rstd; o.y = fmaxf(o.y, 0.01f * o.y);
        o.z = (v.z - mu) * rstd; o.z = fmaxf(o.z, 0.01f * o.z);
        o.w = (v.w - mu) * rstd; o.w = fmaxf(o.w, 0.01f * o.w);
        __stcs(op + (R0 + i) * 32 + lane, o);
    }
}

// ---------------------------------------------------------------------------
extern "C" void kernel_launch(void* const* d_in, const int* in_sizes, int n_in,
                              void* d_out, int out_size) {
    const float* x  = (const float*)d_in[0];
    const float* w1 = (const float*)d_in[1];   // [64, 256]
    const float* w2 = (const float*)d_in[2];   // [256, 64]
    const float* rw = (const float*)d_in[3];   // [256, 1, 3, 3]
    const float* rb = (const float*)d_in[4];   // [256]
    float* out = (float*)d_out;

    // 64KB dynamic smem (> 48KB default) — idempotent, capture-safe
    cudaFuncSetAttribute(supermain_kernel, cudaFuncAttributeMaxDynamicSharedMemorySize,
                         HW * (int)sizeof(float));

    mean_kernel<<<NPLANES, 256>>>(x);
    attn_kernel<<<8, 256>>>(w1, w2);
    supermain_kernel<<<NPLANES, 256, HW * sizeof(float)>>>(x, rw, rb, out);
}

// round 14
// speedup vs baseline: 1.0229x; 1.0229x over previous
#include <cuda_runtime.h>
#include <math.h>

// Problem constants: x[8, 256, 128, 128] fp32
#define NPLANES 2048
#define HW      16384
#define FULL    0xffffffffu

// Scratch (no allocations allowed). Two slots per plane (half 0 / half 1).
__device__ float g_p [2 * NPLANES];   // partial sum of x
__device__ float g_cs[2 * NPLANES];   // partial sum of conv(x) (unscaled)
__device__ float g_cq[2 * NPLANES];   // partial sumsq of conv(x)
__device__ float g_a [NPLANES];       // sigmoid attention scales

__device__ __forceinline__ float4 zero4() { return make_float4(0.f, 0.f, 0.f, 0.f); }

__device__ __forceinline__ float halo_l(float4 v, int lane) {
    float l = __shfl_up_sync(FULL, v.w, 1);
    return (lane == 0) ? 0.f : l;
}
__device__ __forceinline__ float halo_r(float4 v, int lane) {
    float r = __shfl_down_sync(FULL, v.x, 1);
    return (lane == 31) ? 0.f : r;
}

// 3x3 conv producing 4 outputs from float4 rows + halo scalars.
__device__ __forceinline__ float4 conv_row(float4 t, float tl, float tr,
                                            float4 m, float ml, float mr,
                                            float4 b, float bl, float br,
                                            const float* w, float init) {
    float4 o;
    o.x = init; o.y = init; o.z = init; o.w = init;
    o.x = fmaf(tl,  w[0], o.x); o.x = fmaf(t.x, w[1], o.x); o.x = fmaf(t.y, w[2], o.x);
    o.y = fmaf(t.x, w[0], o.y); o.y = fmaf(t.y, w[1], o.y); o.y = fmaf(t.z, w[2], o.y);
    o.z = fmaf(t.y, w[0], o.z); o.z = fmaf(t.z, w[1], o.z); o.z = fmaf(t.w, w[2], o.z);
    o.w = fmaf(t.z, w[0], o.w); o.w = fmaf(t.w, w[1], o.w); o.w = fmaf(tr,  w[2], o.w);
    o.x = fmaf(ml,  w[3], o.x); o.x = fmaf(m.x, w[4], o.x); o.x = fmaf(m.y, w[5], o.x);
    o.y = fmaf(m.x, w[3], o.y); o.y = fmaf(m.y, w[4], o.y); o.y = fmaf(m.z, w[5], o.y);
    o.z = fmaf(m.y, w[3], o.z); o.z = fmaf(m.z, w[4], o.z); o.z = fmaf(m.w, w[5], o.z);
    o.w = fmaf(m.z, w[3], o.w); o.w = fmaf(m.w, w[4], o.w); o.w = fmaf(mr,  w[5], o.w);
    o.x = fmaf(bl,  w[6], o.x); o.x = fmaf(b.x, w[7], o.x); o.x = fmaf(b.y, w[8], o.x);
    o.y = fmaf(b.x, w[6], o.y); o.y = fmaf(b.y, w[7], o.y); o.y = fmaf(b.z, w[8], o.y);
    o.z = fmaf(b.y, w[6], o.z); o.z = fmaf(b.z, w[7], o.z); o.z = fmaf(b.w, w[8], o.z);
    o.w = fmaf(b.z, w[6], o.w); o.w = fmaf(b.w, w[7], o.w); o.w = fmaf(br,  w[8], o.w);
    return o;
}

// ---------------------------------------------------------------------------
// K1: TWO blocks per plane (half-planes of 64 rows). Each warp batch-loads
// ONLY its 8 own rows (each global row read exactly once per block); the
// vertical halo rows are exchanged between warps via an 8KB smem buffer
// (2 boundary rows per warp), ONE barrier total. Block-external halo rows
// (2 per 64) still come from global. Cuts L2-side read traffic ~25%.
// ---------------------------------------------------------------------------
__global__ void __launch_bounds__(256) stats_kernel(const float* __restrict__ x,
                                                     const float* __restrict__ rw) {
    __shared__ float4 shv[16 * 32];            // [warp*2+{0,1}][lane] boundary rows
    int plane = blockIdx.x >> 1, half = blockIdx.x & 1;
    int c = plane & 255;
    int tid = threadIdx.x, lane = tid & 31, wj = tid >> 5;
    int R0 = half * 64 + wj * 8;
    const float4* xp = (const float4*)(x + (size_t)plane * HW);

    // Batched own-row loads (8 independent LDG.128 back-to-back)
    float4 v[8];
#pragma unroll
    for (int i = 0; i < 8; i++) v[i] = xp[(R0 + i) * 32 + lane];

    // Block-external halo rows (edge warps only)
    float4 th = zero4(), bh = zero4();
    if (wj == 0 && R0 != 0)       th = xp[(R0 - 1) * 32 + lane];
    if (wj == 7 && R0 + 8 <= 127) bh = xp[(R0 + 8) * 32 + lane];

    float w[9];
#pragma unroll
    for (int i = 0; i < 9; i++) w[i] = rw[c * 9 + i];

    // Publish boundary rows, then one barrier
    shv[(wj * 2 + 0) * 32 + lane] = v[0];
    shv[(wj * 2 + 1) * 32 + lane] = v[7];

    float psum = 0.f;
#pragma unroll
    for (int i = 0; i < 8; i++) psum += (v[i].x + v[i].y) + (v[i].z + v[i].w);
    __syncthreads();

    if (wj != 0) th = shv[((wj - 1) * 2 + 1) * 32 + lane];   // neighbor's row 7
    if (wj != 7) bh = shv[((wj + 1) * 2 + 0) * 32 + lane];   // neighbor's row 0

    // Horizontal halos, computed once per used row (th, v[0..7], bh)
    float lh[10], rh[10];
    lh[0] = halo_l(th, lane); rh[0] = halo_r(th, lane);
#pragma unroll
    for (int i = 0; i < 8; i++) { lh[i + 1] = halo_l(v[i], lane); rh[i + 1] = halo_r(v[i], lane); }
    lh[9] = halo_l(bh, lane); rh[9] = halo_r(bh, lane);

    float csum = 0.f, csq = 0.f;
#pragma unroll
    for (int i = 0; i < 8; i++) {
        float4 top = (i == 0) ? th : v[i - 1];
        float4 bot = (i == 7) ? bh : v[i + 1];
        float4 o = conv_row(top,  lh[i],     rh[i],
                            v[i], lh[i + 1], rh[i + 1],
                            bot,  lh[i + 2], rh[i + 2],
                            w, 0.f);
        csum += ((o.x + o.y) + (o.z + o.w));
        csq = fmaf(o.x, o.x, csq); csq = fmaf(o.y, o.y, csq);
        csq = fmaf(o.z, o.z, csq); csq = fmaf(o.w, o.w, csq);
    }

#pragma unroll
    for (int o = 16; o; o >>= 1) {
        psum += __shfl_xor_sync(FULL, psum, o);
        csum += __shfl_xor_sync(FULL, csum, o);
        csq  += __shfl_xor_sync(FULL, csq,  o);
    }
    __shared__ float r0[8], r1[8], r2[8];
    if (lane == 0) { r0[wj] = psum; r1[wj] = csum; r2[wj] = csq; }
    __syncthreads();
    if (tid == 0) {
        float t0 = 0.f, t1 = 0.f, t2 = 0.f;
#pragma unroll
        for (int i = 0; i < 8; i++) { t0 += r0[i]; t1 += r1[i]; t2 += r2[i]; }
        int slot = half * NPLANES + plane;
        g_p[slot]  = t0;
        g_cs[slot] = t1;
        g_cq[slot] = t2;
    }
}

// ---------------------------------------------------------------------------
// K2 (fused SE attention): h = leaky(p @ w1^T); a = sigmoid(h @ w2^T).
// ---------------------------------------------------------------------------
__global__ void __launch_bounds__(256) attn_kernel(const float* __restrict__ w1,
                                                    const float* __restrict__ w2) {
    int b = blockIdx.x;
    __shared__ float ps[256];
    __shared__ float hs[64];
    int tid = threadIdx.x;
    int pl = b * 256 + tid;
    ps[tid] = (g_p[pl] + g_p[NPLANES + pl]) * (1.0f / 16384.0f);
    __syncthreads();
    {
        int j = tid >> 2, part = tid & 3;
        const float* wr = w1 + j * 256 + part * 64;
        const float* pr = ps + part * 64;
        float s = 0.f;
#pragma unroll
        for (int cc = 0; cc < 64; cc++) s = fmaf(pr[cc], wr[cc], s);
        s += __shfl_xor_sync(FULL, s, 1);
        s += __shfl_xor_sync(FULL, s, 2);
        if (part == 0) hs[j] = (s > 0.f) ? s : 0.01f * s;
    }
    __syncthreads();
    {
        const float* wr = w2 + tid * 64;
        float s = 0.f;
#pragma unroll
        for (int j = 0; j < 64; j++) s = fmaf(hs[j], wr[j], s);
        g_a[b * 256 + tid] = 1.0f / (1.0f + expf(-s));
    }
}

// ---------------------------------------------------------------------------
// K3: TWO blocks per plane (half-planes), reverse order (ride K1's L2 tail).
// Same smem halo exchange (each x row read once). Conv with FULLY FOLDED
// weights: w' = a*rstd*w, init = (bias-mu)*rstd -> output already
// normalized; epilogue = leaky relu only. __ldcs reads, __stcs stores.
// ---------------------------------------------------------------------------
__global__ void __launch_bounds__(256) main_kernel(const float* __restrict__ x,
                                                    const float* __restrict__ rw,
                                                    const float* __restrict__ rb,
                                                    float* __restrict__ out) {
    __shared__ float4 shv[16 * 32];
    int idx = (2 * NPLANES - 1) - blockIdx.x;
    int bc = idx >> 1, half = idx & 1;
    int c = bc & 255;
    int tid = threadIdx.x, lane = tid & 31, wj = tid >> 5;
    int R0 = half * 64 + wj * 8;
    const float4* xp = (const float4*)(x + (size_t)bc * HW);
    float4* op = (float4*)(out + (size_t)bc * HW);

    // Batched own-row loads first (maximize outstanding loads)
    float4 v[8];
#pragma unroll
    for (int i = 0; i < 8; i++) v[i] = __ldcs(xp + (R0 + i) * 32 + lane);
    float4 th = zero4(), bh = zero4();
    if (wj == 0 && R0 != 0)       th = __ldcs(xp + (R0 - 1) * 32 + lane);
    if (wj == 7 && R0 + 8 <= 127) bh = __ldcs(xp + (R0 + 8) * 32 + lane);

    float a = g_a[bc];
    float bias = rb[c];
    float csum = g_cs[bc] + g_cs[NPLANES + bc];
    float csq  = g_cq[bc] + g_cq[NPLANES + bc];
    float mu_c  = csum * (1.0f / 16384.0f);
    float var_c = csq * (1.0f / 16384.0f) - mu_c * mu_c;
    float mu   = a * mu_c + bias;
    float rstd = rsqrtf(a * a * var_c + 1e-5f);
    float scale = a * rstd;
    float init = (bias - mu) * rstd;

    float w[9];
#pragma unroll
    for (int i = 0; i < 9; i++) w[i] = scale * rw[c * 9 + i];

    // Publish boundary rows, one barrier, fetch neighbor halos
    shv[(wj * 2 + 0) * 32 + lane] = v[0];
    shv[(wj * 2 + 1) * 32 + lane] = v[7];
    __syncthreads();
    if (wj != 0) th = shv[((wj - 1) * 2 + 1) * 32 + lane];
    if (wj != 7) bh = shv[((wj + 1) * 2 + 0) * 32 + lane];

    float lh[10], rh[10];
    lh[0] = halo_l(th, lane); rh[0] = halo_r(th, lane);
#pragma unroll
    for (int i = 0; i < 8; i++) { lh[i + 1] = halo_l(v[i], lane); rh[i + 1] = halo_r(v[i], lane); }
    lh[9] = halo_l(bh, lane); rh[9] = halo_r(bh, lane);

#pragma unroll
    for (int i = 0; i < 8; i++) {
        float4 top = (i == 0) ? th : v[i - 1];
        float4 bot = (i == 7) ? bh : v[i + 1];
        float4 o = conv_row(top,  lh[i],     rh[i],
                            v[i], lh[i + 1], rh[i + 1],
                            bot,  lh[i + 2], rh[i + 2],
                            w, init);                    // already normalized
        o.x = fmaxf(o.x, 0.01f * o.x);
        o.y = fmaxf(o.y, 0.01f * o.y);
        o.z = fmaxf(o.z, 0.01f * o.z);
        o.w = fmaxf(o.w, 0.01f * o.w);
        __stcs(op + (R0 + i) * 32 + lane, o);
    }
}

// ---------------------------------------------------------------------------
extern "C" void kernel_launch(void* const* d_in, const int* in_sizes, int n_in,
                              void* d_out, int out_size) {
    const float* x  = (const float*)d_in[0];
    const float* w1 = (const float*)d_in[1];   // [64, 256]
    const float* w2 = (const float*)d_in[2];   // [256, 64]
    const float* rw = (const float*)d_in[3];   // [256, 1, 3, 3]
    const float* rb = (const float*)d_in[4];   // [256]
    float* out = (float*)d_out;

    stats_kernel<<<2 * NPLANES, 256>>>(x, rw);
    attn_kernel<<<8, 256>>>(w1, w2);
    main_kernel<<<2 * NPLANES, 256>>>(x, rw, rb, out);
}